// round 17
// baseline (speedup 1.0000x reference)
#include <cuda_runtime.h>
#include <cuda.h>
#include <cuda_fp16.h>
#include <cstdint>
#include <cstring>

// Problem shape (fixed for this dataset entry)
#define BB 8
#define CC 16
#define HH 512
#define WW 512
#define HWP (HH * WW)           // 262144 pixels per batch
#define NPIX (BB * HWP)         // 2,097,152 total pixels

// Channel-last fp16 scratch accumulator: [B, HW, C] == 3D tensor
// [B][H][W*C halves]. One pixel's 4 corner cells form a 64Bx2 box.
// 67 MB -> fits in L2. Zero-invariant: starts zeroed; the transpose restores
// zeros via ONE cp.async.bulk store of 8KB zeros per block (race-free:
// issued only after pre-barrier STGs pinned every scratch load's completion).
__device__ __align__(256) __half2 g_scratch[(size_t)BB * HWP * (CC / 2)];

// Tensormap for the scratch tensor (filled at static-init).
__device__ __align__(128) CUtensorMap g_tmap;

__device__ __forceinline__ uint32_t smem_u32(const void* p) {
    uint32_t a;
    asm("{ .reg .u64 t; cvta.to.shared.u64 t, %1; cvt.u32.u64 %0, t; }"
        : "=r"(a) : "l"(p));
    return a;
}

// ---------------------------------------------------------------------------
// Static init: second stream + events (fork) and the TMA tensormap.
// ---------------------------------------------------------------------------
static cudaStream_t g_s2 = nullptr;
static cudaEvent_t  g_evA = nullptr;
static cudaEvent_t  g_evB = nullptr;
static cudaEvent_t  g_evJoin = nullptr;
static bool         g_forkOK = false;
static bool         g_tmapOK = false;

typedef CUresult (*EncodeTiledFn)(
    CUtensorMap*, CUtensorMapDataType, cuuint32_t, void*,
    const cuuint64_t*, const cuuint64_t*, const cuuint32_t*, const cuuint32_t*,
    CUtensorMapInterleave, CUtensorMapSwizzle, CUtensorMapL2promotion,
    CUtensorMapFloatOOBfill);

namespace {
struct Init {
    Init() {
        cudaError_t e1 = cudaStreamCreateWithFlags(&g_s2, cudaStreamNonBlocking);
        cudaError_t e2 = cudaEventCreateWithFlags(&g_evA, cudaEventDisableTiming);
        cudaError_t e3 = cudaEventCreateWithFlags(&g_evB, cudaEventDisableTiming);
        cudaError_t e4 = cudaEventCreateWithFlags(&g_evJoin, cudaEventDisableTiming);
        g_forkOK = (e1 == cudaSuccess) && (e2 == cudaSuccess) &&
                   (e3 == cudaSuccess) && (e4 == cudaSuccess);

        do {
            void* sptr = nullptr;
            if (cudaGetSymbolAddress(&sptr, g_scratch) != cudaSuccess) break;

            EncodeTiledFn encode = nullptr;
#if CUDART_VERSION >= 12000
            cudaDriverEntryPointQueryResult qr;
            if (cudaGetDriverEntryPoint("cuTensorMapEncodeTiled",
                                        (void**)&encode,
                                        cudaEnableDefault, &qr) != cudaSuccess ||
                qr != cudaDriverEntryPointSuccess || !encode) break;
#else
            if (cudaGetDriverEntryPoint("cuTensorMapEncodeTiled",
                                        (void**)&encode,
                                        cudaEnableDefault) != cudaSuccess ||
                !encode) break;
#endif
            CUtensorMap h_tmap;
            cuuint64_t dims[3]    = { (cuuint64_t)(WW * CC),
                                      (cuuint64_t)HH,
                                      (cuuint64_t)BB };
            cuuint64_t strides[2] = { (cuuint64_t)WW * CC * 2,
                                      (cuuint64_t)HH * WW * CC * 2 };
            cuuint32_t box[3]     = { 32, 2, 1 };
            cuuint32_t estr[3]    = { 1, 1, 1 };
            CUresult r = encode(&h_tmap, CU_TENSOR_MAP_DATA_TYPE_FLOAT16, 3,
                                sptr, dims, strides, box, estr,
                                CU_TENSOR_MAP_INTERLEAVE_NONE,
                                CU_TENSOR_MAP_SWIZZLE_NONE,
                                CU_TENSOR_MAP_L2_PROMOTION_L2_128B,
                                CU_TENSOR_MAP_FLOAT_OOB_FILL_NONE);
            if (r != CUDA_SUCCESS) break;
            if (cudaMemcpyToSymbol(g_tmap, &h_tmap, sizeof(CUtensorMap)) !=
                cudaSuccess) break;
            g_tmapOK = true;
        } while (0);
    }
};
static Init g_init;
}

// ---------------------------------------------------------------------------
// Splat via TMA tensor reduce, TWO adjacent pixels per thread.
// Halves LDG instruction count (LDG.64 per channel pair) and amortizes all
// index math / commit / wait, attacking the measured issue(51%)/alu(55%)
// bound. 128 threads x 256B staging = 32KB static smem.
// ---------------------------------------------------------------------------
__global__ void __launch_bounds__(128) splat_tensor_kernel(
    const float* __restrict__ im0,   // [B, C, H, W]
    const float* __restrict__ flow,  // [B, H, W, 2]
    int base)                        // pixel base (multiple of 256)
{
    __shared__ __align__(16) char sm[128 * 256];

    int t  = blockIdx.x * blockDim.x + threadIdx.x;
    int p2 = base + t * 2;           // first of two adjacent pixels

    int b = p2 / HWP;
    int p = p2 - b * HWP;            // even; p and p+1 share a row
    int h = p >> 9;
    int w = p & (WW - 1);

    // Flow for both pixels: one float4.
    float4 fl = __ldcs(reinterpret_cast<const float4*>(flow + (size_t)p2 * 2));
    float dxs[2] = { fl.x, fl.z };
    float dys[2] = { fl.y, fl.w };

    // Channel values for both pixels: 16x LDG.64 (p, p+1 contiguous).
    float2 v2[CC];
    const float* src = im0 + (size_t)b * CC * HWP + p;
#pragma unroll
    for (int c = 0; c < CC; c++)
        v2[c] = __ldcs(reinterpret_cast<const float2*>(src + (size_t)c * HWP));

    char* my = sm + threadIdx.x * 256;
    uint32_t saddr = smem_u32(my);

    int cxs[2], cys[2];

#pragma unroll
    for (int j = 0; j < 2; j++) {
        float x = (float)(w + j) + dxs[j];
        float y = (float)h + dys[j];

        float x0f = floorf(x);
        float y0f = floorf(y);
        int   x0  = (int)x0f;
        int   y0  = (int)y0f;
        float fx  = x - x0f;
        float fy  = y - y0f;

        // Clamped box origin (always in-bounds; tensor reduce traps on OOB).
        int cx = min(max(x0, 0), WW - 2);
        int cy = min(max(y0, 0), HH - 2);
        cxs[j] = cx;
        cys[j] = cy;
        int dx = x0 - cx;
        int dy = y0 - cy;

        float wx0 = 1.0f - fx, wx1 = fx;
        float wy0 = 1.0f - fy, wy1 = fy;
        float colw[2], roww[2];
#pragma unroll
        for (int k = 0; k < 2; k++) {
            int o = k - dx;
            colw[k] = (o == 0) ? wx0 : ((o == 1) ? wx1 : 0.0f);
        }
#pragma unroll
        for (int r = 0; r < 2; r++) {
            int o = r - dy;
            roww[r] = (o == 0) ? wy0 : ((o == 1) ? wy1 : 0.0f);
        }

        // Stage this pixel's 64Bx2 box at my + j*128.
        char* box = my + j * 128;
#pragma unroll
        for (int r = 0; r < 2; r++) {
#pragma unroll
            for (int k = 0; k < 2; k++) {
                float wgt = roww[r] * colw[k];
                unsigned hh[8];
#pragma unroll
                for (int i = 0; i < 8; i++) {
                    float a = ((j == 0) ? v2[2 * i].x     : v2[2 * i].y)     * wgt;
                    float c = ((j == 0) ? v2[2 * i + 1].x : v2[2 * i + 1].y) * wgt;
                    __half2 tt = __float22half2_rn(make_float2(a, c));
                    hh[i] = *reinterpret_cast<unsigned*>(&tt);
                }
                uint4* cell = reinterpret_cast<uint4*>(box + r * 64 + k * 32);
                cell[0] = make_uint4(hh[0], hh[1], hh[2], hh[3]);
                cell[1] = make_uint4(hh[4], hh[5], hh[6], hh[7]);
            }
        }
    }

    // Order the generic smem stores before the async-proxy bulk reads.
    asm volatile("fence.proxy.async.shared::cta;" ::: "memory");

#pragma unroll
    for (int j = 0; j < 2; j++) {
        asm volatile(
            "cp.reduce.async.bulk.tensor.3d.global.shared::cta.add.tile.bulk_group "
            "[%0, {%1, %2, %3}], [%4];"
            :: "l"(&g_tmap), "r"(cxs[j] * CC), "r"(cys[j]), "r"(b),
               "r"(saddr + j * 128)
            : "memory");
    }

    asm volatile("cp.async.bulk.commit_group;" ::: "memory");
    asm volatile("cp.async.bulk.wait_group 0;" ::: "memory");
}

// ---------------------------------------------------------------------------
// Fallback splat (R9-proven linear bulk-reduce form) if tensormap init fails.
// ---------------------------------------------------------------------------
__global__ void __launch_bounds__(256) splat_kernel(
    const float* __restrict__ im0,
    const float* __restrict__ flow,
    int base)
{
    __shared__ __align__(16) char sm[256 * 128];

    int idx = base + blockIdx.x * blockDim.x + threadIdx.x;

    int b = idx / HWP;
    int p = idx - b * HWP;
    int h = p >> 9;
    int w = p & (WW - 1);

    float2 f = __ldcs(reinterpret_cast<const float2*>(flow) + idx);
    float x = (float)w + f.x;
    float y = (float)h + f.y;

    float x0f = floorf(x);
    float y0f = floorf(y);
    int   x0  = (int)x0f;
    int   y0  = (int)y0f;
    float fx  = x - x0f;
    float fy  = y - y0f;

    float w00 = (1.0f - fx) * (1.0f - fy);
    float w01 = fx * (1.0f - fy);
    float w10 = (1.0f - fx) * fy;
    float w11 = fx * fy;

    float v[CC];
    const float* src = im0 + (size_t)b * CC * HWP + p;
#pragma unroll
    for (int c = 0; c < CC; c++) v[c] = __ldcs(src + (size_t)c * HWP);

    char* my = sm + threadIdx.x * 128;
    float wts[4] = { w00, w01, w10, w11 };
#pragma unroll
    for (int k = 0; k < 4; k++) {
        float wgt = wts[k];
        unsigned hh[8];
#pragma unroll
        for (int i = 0; i < 8; i++) {
            __half2 t = __float22half2_rn(
                make_float2(v[2 * i] * wgt, v[2 * i + 1] * wgt));
            hh[i] = *reinterpret_cast<unsigned*>(&t);
        }
        uint4* cell = reinterpret_cast<uint4*>(my + k * 32);
        cell[0] = make_uint4(hh[0], hh[1], hh[2], hh[3]);
        cell[1] = make_uint4(hh[4], hh[5], hh[6], hh[7]);
    }

    asm volatile("fence.proxy.async.shared::cta;" ::: "memory");

    uint32_t saddr = smem_u32(my);
    __half2* sbase = g_scratch + (size_t)b * HWP * (CC / 2);

    bool vx0 = (x0 >= 0) && (x0 < WW);
    bool vx1 = (x0 + 1 >= 0) && (x0 + 1 < WW);

#pragma unroll
    for (int r = 0; r < 2; r++) {
        int yi = y0 + r;
        if (yi < 0 || yi >= HH) continue;
        uint32_t srow = saddr + r * 64;
        if (vx0 && vx1) {
            const __half2* g = sbase + ((size_t)(yi * WW + x0)) * (CC / 2);
            asm volatile(
                "cp.reduce.async.bulk.global.shared::cta.bulk_group.add.noftz.f16 "
                "[%0], [%1], 64;"
                :: "l"(g), "r"(srow) : "memory");
        } else if (vx0) {
            const __half2* g = sbase + ((size_t)(yi * WW + x0)) * (CC / 2);
            asm volatile(
                "cp.reduce.async.bulk.global.shared::cta.bulk_group.add.noftz.f16 "
                "[%0], [%1], 32;"
                :: "l"(g), "r"(srow) : "memory");
        } else if (vx1) {
            const __half2* g = sbase + ((size_t)(yi * WW + x0 + 1)) * (CC / 2);
            asm volatile(
                "cp.reduce.async.bulk.global.shared::cta.bulk_group.add.noftz.f16 "
                "[%0], [%1], 32;"
                :: "l"(g), "r"(srow + 32) : "memory");
        }
    }

    asm volatile("cp.async.bulk.commit_group;" ::: "memory");
    asm volatile("cp.async.bulk.wait_group 0;" ::: "memory");
}

// ---------------------------------------------------------------------------
// Transpose + fused TMA zero-restore (R16-proven, race-free):
//   STS zeros -> LDG scratch -> STG out (pins load completion) ->
//   __syncthreads -> tid0 bulk zero-store -> commit/wait.
// ---------------------------------------------------------------------------
__global__ void __launch_bounds__(256) transpose_kernel(
    float* __restrict__ out, int base)
{
    __shared__ __align__(16) uint4 szero[512];   // 8KB of zeros

    int tid = threadIdx.x;
    int idx = base + blockIdx.x * blockDim.x + tid;

    int b = idx / HWP;
    int p = idx - b * HWP;

    uint4 z = make_uint4(0, 0, 0, 0);
    szero[2 * tid]     = z;
    szero[2 * tid + 1] = z;

    const uint4* src =
        reinterpret_cast<const uint4*>(g_scratch + (size_t)idx * (CC / 2));
    uint4 q0 = src[0];
    uint4 q1 = src[1];

    float2 c01 = __half22float2(*reinterpret_cast<__half2*>(&q0.x));
    float2 c23 = __half22float2(*reinterpret_cast<__half2*>(&q0.y));
    float2 c45 = __half22float2(*reinterpret_cast<__half2*>(&q0.z));
    float2 c67 = __half22float2(*reinterpret_cast<__half2*>(&q0.w));
    float2 c89 = __half22float2(*reinterpret_cast<__half2*>(&q1.x));
    float2 cab = __half22float2(*reinterpret_cast<__half2*>(&q1.y));
    float2 ccd = __half22float2(*reinterpret_cast<__half2*>(&q1.z));
    float2 cef = __half22float2(*reinterpret_cast<__half2*>(&q1.w));

    float* dst = out + (size_t)b * CC * HWP + p;
    __stcs(dst + (size_t)0  * HWP, c01.x);
    __stcs(dst + (size_t)1  * HWP, c01.y);
    __stcs(dst + (size_t)2  * HWP, c23.x);
    __stcs(dst + (size_t)3  * HWP, c23.y);
    __stcs(dst + (size_t)4  * HWP, c45.x);
    __stcs(dst + (size_t)5  * HWP, c45.y);
    __stcs(dst + (size_t)6  * HWP, c67.x);
    __stcs(dst + (size_t)7  * HWP, c67.y);
    __stcs(dst + (size_t)8  * HWP, c89.x);
    __stcs(dst + (size_t)9  * HWP, c89.y);
    __stcs(dst + (size_t)10 * HWP, cab.x);
    __stcs(dst + (size_t)11 * HWP, cab.y);
    __stcs(dst + (size_t)12 * HWP, ccd.x);
    __stcs(dst + (size_t)13 * HWP, ccd.y);
    __stcs(dst + (size_t)14 * HWP, cef.x);
    __stcs(dst + (size_t)15 * HWP, cef.y);

    __syncthreads();   // all threads' scratch loads completed; zeros visible

    if (tid == 0) {
        asm volatile("fence.proxy.async.shared::cta;" ::: "memory");
        const __half2* gdst =
            g_scratch + (size_t)(base + blockIdx.x * 256) * (CC / 2);
        uint32_t saddr = smem_u32(szero);
        asm volatile(
            "cp.async.bulk.global.shared::cta.bulk_group [%0], [%1], 8192;"
            :: "l"(gdst), "r"(saddr) : "memory");
        asm volatile("cp.async.bulk.commit_group;" ::: "memory");
        asm volatile("cp.async.bulk.wait_group 0;" ::: "memory");
    }
}

extern "C" void kernel_launch(void* const* d_in, const int* in_sizes, int n_in,
                              void* d_out, int out_size)
{
    // Identify inputs by size (im0 = B*C*H*W, flow = B*H*W*2).
    const float* im0;
    const float* flow;
    if (in_sizes[0] == BB * CC * HWP) {
        im0  = (const float*)d_in[0];
        flow = (const float*)d_in[1];
    } else {
        im0  = (const float*)d_in[1];
        flow = (const float*)d_in[0];
    }
    float* out = (float*)d_out;

    const int threads = 256;

    // Batch groups: A = 0-2, B = 3-5, C = 6-7.
    const int baseA = 0,        npixA = 3 * HWP;
    const int baseB = 3 * HWP,  npixB = 3 * HWP;
    const int baseC = 6 * HWP,  npixC = 2 * HWP;

    auto launch_splat = [&](int base, int npix, cudaStream_t s) {
        if (g_tmapOK)
            // 2 pixels/thread, 128 threads/block -> npix/256 blocks.
            splat_tensor_kernel<<<npix / 256, 128, 0, s>>>(im0, flow, base);
        else
            splat_kernel<<<npix / threads, threads, 0, s>>>(im0, flow, base);
    };

    if (g_forkOK) {
        // 3-stage pipeline, zero-restore fused into transpose (no memsets).
        launch_splat(baseA, npixA, 0);                               // S_A
        cudaEventRecord(g_evA, 0);
        launch_splat(baseB, npixB, 0);                               // S_B
        cudaEventRecord(g_evB, 0);
        launch_splat(baseC, npixC, 0);                               // S_C

        cudaStreamWaitEvent(g_s2, g_evA, 0);
        transpose_kernel<<<npixA / threads, threads, 0, g_s2>>>(out, baseA);
        cudaStreamWaitEvent(g_s2, g_evB, 0);
        transpose_kernel<<<npixB / threads, threads, 0, g_s2>>>(out, baseB);
        cudaEventRecord(g_evJoin, g_s2);

        transpose_kernel<<<npixC / threads, threads>>>(out, baseC);  // T_C
        cudaStreamWaitEvent(0, g_evJoin, 0);                         // join
    } else {
        launch_splat(0, NPIX / 2, 0);
        launch_splat(NPIX / 2, NPIX / 2, 0);
        transpose_kernel<<<(NPIX / 2) / threads, threads>>>(out, 0);
        transpose_kernel<<<(NPIX / 2) / threads, threads>>>(out, NPIX / 2);
    }
}